// round 1
// baseline (speedup 1.0000x reference)
#include <cuda_runtime.h>
#include <cstddef>

// Grefenstette stack forward, closed-form reformulation.
//
//   s_t[j] = relu(d_j - relu(max_{j<tau<=t} G_tau - H_j))
//     G_tau = P_tau - D_{tau-1},  H_j = P_j - D_j,
//     P = cumsum(u), D = cumsum(d)
//   w_t[j] = min(1, R_t[j]) - min(1, R_t[j+1]),  R = suffix-sum of s_t
//   out[t,b,:] = sum_j w_t[j] * v[j,b,:]
//
// w_t is nonzero only on a contiguous top range; a short downward scan with
// early exit (accumulated strength >= 1) finds it.

#define TT 512
#define BB 128
#define EE 256

#define WARPS 8
#define TPW 4   // t-values per warp

// Scratch (allocation-free): per-batch transposed G/H/d, float, 768 KB total.
__device__ float g_G[BB][TT];
__device__ float g_H[BB][TT];
__device__ float g_D[BB][TT];

// ---------------------------------------------------------------------------
// Kernel 1: per-batch prefix sums in fp64 (Hillis-Steele in smem), write
// G, H, d transposed to [B][T] so the main kernel streams them contiguously.
// One block per batch, 512 threads (one per timestep).
// ---------------------------------------------------------------------------
__global__ __launch_bounds__(TT) void scan_kernel(const float* __restrict__ u,
                                                  const float* __restrict__ d) {
    __shared__ double su[TT];
    __shared__ double sd[TT];
    const int b = blockIdx.x;
    const int t = threadIdx.x;

    const float uv = u[t * BB + b];
    const float dv = d[t * BB + b];
    su[t] = (double)uv;
    sd[t] = (double)dv;
    __syncthreads();

    #pragma unroll
    for (int off = 1; off < TT; off <<= 1) {
        double a = (t >= off) ? su[t - off] : 0.0;
        double c = (t >= off) ? sd[t - off] : 0.0;
        __syncthreads();
        su[t] += a;
        sd[t] += c;
        __syncthreads();
    }

    const double P     = su[t];
    const double Dc    = sd[t];
    const double Dprev = (t > 0) ? sd[t - 1] : 0.0;

    g_G[b][t] = (float)(P - Dprev);  // G_t = P_t - D_{t-1}
    g_H[b][t] = (float)(P - Dc);     // H_t = P_t - D_t
    g_D[b][t] = dv;
}

// ---------------------------------------------------------------------------
// Kernel 2: one warp per TPW consecutive timesteps of one batch.
// Backward scan from the stack top; each live slot contributes
// w * v[j,b,:] via two coalesced float4 loads per lane (E=256).
// ---------------------------------------------------------------------------
__global__ __launch_bounds__(WARPS * 32) void stack_kernel(
    const float* __restrict__ v, float* __restrict__ out) {
    __shared__ float sG[TT];
    __shared__ float sH[TT];
    __shared__ float sD[TT];

    const int b   = blockIdx.y;
    const int tid = threadIdx.x;

    for (int i = tid; i < TT; i += WARPS * 32) {
        sG[i] = g_G[b][i];
        sH[i] = g_H[b][i];
        sD[i] = g_D[b][i];
    }
    __syncthreads();

    const int warp = tid >> 5;
    const int lane = tid & 31;
    const int tbase = (blockIdx.x * WARPS + warp) * TPW;

    const float4* __restrict__ v4 = reinterpret_cast<const float4*>(v);
    float4* __restrict__ o4       = reinterpret_cast<float4*>(out);

    #pragma unroll
    for (int i = 0; i < TPW; ++i) {
        const int t = tbase + i;

        float4 r0 = make_float4(0.f, 0.f, 0.f, 0.f);
        float4 r1 = make_float4(0.f, 0.f, 0.f, 0.f);

        float M   = -1e30f;  // max of G over (j, t]; empty for j == t
        float acc = 0.f;     // suffix strength already consumed (R_t[j+1])

        for (int j = t; j >= 0; --j) {
            const float s = fmaxf(sD[j] - fmaxf(M - sH[j], 0.f), 0.f);
            M = fmaxf(M, sG[j]);  // fold G_j in for the next (lower) slot
            if (s > 0.f) {
                const float w = fminf(acc + s, 1.f) - acc;  // acc < 1 here
                acc += s;

                const float4* vp = v4 + ((size_t)j * BB + b) * (EE / 4);
                const float4 a0 = __ldg(vp + lane);
                const float4 a1 = __ldg(vp + lane + 32);
                r0.x = fmaf(w, a0.x, r0.x);
                r0.y = fmaf(w, a0.y, r0.y);
                r0.z = fmaf(w, a0.z, r0.z);
                r0.w = fmaf(w, a0.w, r0.w);
                r1.x = fmaf(w, a1.x, r1.x);
                r1.y = fmaf(w, a1.y, r1.y);
                r1.z = fmaf(w, a1.z, r1.z);
                r1.w = fmaf(w, a1.w, r1.w);

                if (acc >= 1.f) break;  // top unit fully read
            }
        }

        float4* op = o4 + ((size_t)t * BB + b) * (EE / 4);
        op[lane]      = r0;
        op[lane + 32] = r1;
    }
}

extern "C" void kernel_launch(void* const* d_in, const int* in_sizes, int n_in,
                              void* d_out, int out_size) {
    const float* v = (const float*)d_in[0];  // [T,B,E]
    const float* u = (const float*)d_in[1];  // [T,B]
    const float* d = (const float*)d_in[2];  // [T,B]
    float* out     = (float*)d_out;          // [T,B,E]

    scan_kernel<<<BB, TT>>>(u, d);

    dim3 grid(TT / (WARPS * TPW), BB);
    stack_kernel<<<grid, WARPS * 32>>>(v, out);
}

// round 2
// speedup vs baseline: 3.8009x; 3.8009x over previous
#include <cuda_runtime.h>
#include <cstddef>

// Grefenstette stack forward, closed-form reformulation.
//
//   s_t[j] = relu(d_j - relu(max_{j<tau<=t} G_tau - H_j))
//     G_tau = P_tau - D_{tau-1},  H_j = P_j - D_j,
//     P = cumsum(u), D = cumsum(d)
//   w_t[j] = min(1, R_t[j]) - min(1, R_t[j+1]),  R = suffix-sum of s_t
//   out[t,b,:] = sum_j w_t[j] * v[j,b,:]
//
// Phase 1 (per batch): fp64 prefix sums + per-t scalar scan emitting a compact
// (w, j) pair list (top-of-stack read set, usually ~3 entries).
// Phase 2: pure sparse gather, one warp per (t,b).

#define TT 512
#define BB 128
#define EE 256

#define K 16                    // max pairs stored per (t,b)
#define OVER_FLAG 0x10000

#define WARPS 8                 // gather warps per block

// Allocation-free scratch.
__device__ float  g_G[BB][TT];
__device__ float  g_H[BB][TT];
__device__ float  g_D[BB][TT];
__device__ float2 g_pairs[(size_t)TT * BB * K];   // (w, bitcast j)
__device__ int    g_cnt[TT * BB];                 // count | OVER_FLAG
__device__ int    g_jres[TT * BB];                // resume j (overflow only)
__device__ float2 g_resume[TT * BB];              // (M, acc) at cutoff

// ---------------------------------------------------------------------------
// Kernel 1: per-batch fp64 Hillis-Steele scan, then each thread t runs the
// backward strength scan in smem and emits its (w, j) pairs.
// One block per batch, 512 threads.
// ---------------------------------------------------------------------------
__global__ __launch_bounds__(TT) void scan_weights_kernel(
    const float* __restrict__ u, const float* __restrict__ d) {
    __shared__ double su[TT];
    __shared__ double sd[TT];
    __shared__ float  sG[TT];
    __shared__ float  sH[TT];
    __shared__ float  sD[TT];

    const int b = blockIdx.x;
    const int t = threadIdx.x;

    const float uv = u[t * BB + b];
    const float dv = d[t * BB + b];
    su[t] = (double)uv;
    sd[t] = (double)dv;
    __syncthreads();

    #pragma unroll
    for (int off = 1; off < TT; off <<= 1) {
        double a = (t >= off) ? su[t - off] : 0.0;
        double c = (t >= off) ? sd[t - off] : 0.0;
        __syncthreads();
        su[t] += a;
        sd[t] += c;
        __syncthreads();
    }

    const double P     = su[t];
    const double Dc    = sd[t];
    const double Dprev = (t > 0) ? sd[t - 1] : 0.0;

    const float G = (float)(P - Dprev);
    const float H = (float)(P - Dc);
    sG[t] = G;
    sH[t] = H;
    sD[t] = dv;
    g_G[b][t] = G;      // kept for the rare overflow resume path
    g_H[b][t] = H;
    g_D[b][t] = dv;
    __syncthreads();

    // Backward scan from the stack top, emit (w, j) until 1 unit is read.
    float M   = -1e30f;  // max of G over (j, t]
    float acc = 0.f;     // strength consumed so far (R_t[j+1])
    int   cnt = 0;
    float2* pp = &g_pairs[((size_t)t * BB + b) * K];

    int j;
    for (j = t; j >= 0; --j) {
        const float s = fmaxf(sD[j] - fmaxf(M - sH[j], 0.f), 0.f);
        M = fmaxf(M, sG[j]);
        if (s > 0.f) {
            const float w = fminf(acc + s, 1.f) - acc;
            acc += s;
            pp[cnt++] = make_float2(w, __int_as_float(j));
            if (acc >= 1.f) break;
            if (cnt == K) break;
        }
    }

    const int  idx  = t * BB + b;
    const bool over = (cnt == K) && (acc < 1.f) && (j > 0);
    g_cnt[idx] = cnt | (over ? OVER_FLAG : 0);
    if (over) {
        g_jres[idx]   = j - 1;
        g_resume[idx] = make_float2(M, acc);
    }
}

// ---------------------------------------------------------------------------
// Kernel 2: sparse gather. One warp per (t, b); lanes cover E with float4.
// ---------------------------------------------------------------------------
__global__ __launch_bounds__(WARPS * 32) void gather_kernel(
    const float* __restrict__ v, float* __restrict__ out) {
    const int tid  = threadIdx.x;
    const int warp = tid >> 5;
    const int lane = tid & 31;
    const int t    = blockIdx.x * WARPS + warp;
    const int b    = blockIdx.y;
    const int idx  = t * BB + b;

    const float4* __restrict__ v4 = reinterpret_cast<const float4*>(v);
    float4* __restrict__ o4       = reinterpret_cast<float4*>(out);

    float4 r0 = make_float4(0.f, 0.f, 0.f, 0.f);
    float4 r1 = make_float4(0.f, 0.f, 0.f, 0.f);

    const int craw = g_cnt[idx];
    const int cnt  = craw & 0xFFFF;
    const float2* __restrict__ pp = &g_pairs[(size_t)idx * K];

    for (int k = 0; k < cnt; ++k) {
        const float2 p = pp[k];                 // broadcast (same addr all lanes)
        const float  w = p.x;
        const int    j = __float_as_int(p.y);
        const float4* vp = v4 + ((size_t)j * BB + b) * (EE / 4);
        const float4 a0 = __ldg(vp + lane);
        const float4 a1 = __ldg(vp + lane + 32);
        r0.x = fmaf(w, a0.x, r0.x);
        r0.y = fmaf(w, a0.y, r0.y);
        r0.z = fmaf(w, a0.z, r0.z);
        r0.w = fmaf(w, a0.w, r0.w);
        r1.x = fmaf(w, a1.x, r1.x);
        r1.y = fmaf(w, a1.y, r1.y);
        r1.z = fmaf(w, a1.z, r1.z);
        r1.w = fmaf(w, a1.w, r1.w);
    }

    if (craw & OVER_FLAG) {  // rare: continue the scan past K pairs
        const float2 rs = g_resume[idx];
        float M   = rs.x;
        float acc = rs.y;
        for (int j = g_jres[idx]; j >= 0; --j) {
            const float s = fmaxf(g_D[b][j] - fmaxf(M - g_H[b][j], 0.f), 0.f);
            M = fmaxf(M, g_G[b][j]);
            if (s > 0.f) {
                const float w = fminf(acc + s, 1.f) - acc;
                acc += s;
                const float4* vp = v4 + ((size_t)j * BB + b) * (EE / 4);
                const float4 a0 = __ldg(vp + lane);
                const float4 a1 = __ldg(vp + lane + 32);
                r0.x = fmaf(w, a0.x, r0.x);
                r0.y = fmaf(w, a0.y, r0.y);
                r0.z = fmaf(w, a0.z, r0.z);
                r0.w = fmaf(w, a0.w, r0.w);
                r1.x = fmaf(w, a1.x, r1.x);
                r1.y = fmaf(w, a1.y, r1.y);
                r1.z = fmaf(w, a1.z, r1.z);
                r1.w = fmaf(w, a1.w, r1.w);
                if (acc >= 1.f) break;
            }
        }
    }

    float4* op = o4 + ((size_t)t * BB + b) * (EE / 4);
    op[lane]      = r0;
    op[lane + 32] = r1;
}

extern "C" void kernel_launch(void* const* d_in, const int* in_sizes, int n_in,
                              void* d_out, int out_size) {
    const float* v = (const float*)d_in[0];  // [T,B,E]
    const float* u = (const float*)d_in[1];  // [T,B]
    const float* d = (const float*)d_in[2];  // [T,B]
    float* out     = (float*)d_out;          // [T,B,E]

    scan_weights_kernel<<<BB, TT>>>(u, d);

    dim3 grid(TT / WARPS, BB);
    gather_kernel<<<grid, WARPS * 32>>>(v, out);
}

// round 3
// speedup vs baseline: 5.6396x; 1.4837x over previous
#include <cuda_runtime.h>
#include <cstddef>

// Grefenstette stack forward, closed-form reformulation.
//
//   s_t[j] = relu(d_j - relu(M_{j,t} - H_j)),  M_{j,t} = max_{j<tau<=t} G_tau
//     G_tau = P_tau - D_{tau-1},  H_j = P_j - D_j,  P = cumsum(u), D = cumsum(d)
//   w_t[j] = min(1, R_t[j]) - min(1, R_t[j+1]),  R = suffix-sum of s_t
//   out[t,b,:] = sum_j w_t[j] * v[j,b,:]
//
// Kernel 1: per-batch fp64 prefix sums -> G, H, D transposed [B][T].
// Kernel 2: one warp per (t,b). Weights via warp-scans over 32-slot chunks
// (exclusive max-scan for M, exclusive sum-scan for acc), then sparse
// coalesced float4 gather of the few contributing v rows.

#define TT 512
#define BB 128
#define EE 256

#define WARPS 8
#define FULL 0xFFFFFFFFu

__device__ float g_G[BB][TT];
__device__ float g_H[BB][TT];
__device__ float g_D[BB][TT];

// ---------------------------------------------------------------------------
// Kernel 1: fp64 Hillis-Steele prefix sums. One block per batch, 512 threads.
// ---------------------------------------------------------------------------
__global__ __launch_bounds__(TT) void scan_kernel(const float* __restrict__ u,
                                                  const float* __restrict__ d) {
    __shared__ double su[TT];
    __shared__ double sd[TT];
    const int b = blockIdx.x;
    const int t = threadIdx.x;

    const float uv = u[t * BB + b];
    const float dv = d[t * BB + b];
    su[t] = (double)uv;
    sd[t] = (double)dv;
    __syncthreads();

    #pragma unroll
    for (int off = 1; off < TT; off <<= 1) {
        double a = (t >= off) ? su[t - off] : 0.0;
        double c = (t >= off) ? sd[t - off] : 0.0;
        __syncthreads();
        su[t] += a;
        sd[t] += c;
        __syncthreads();
    }

    const double P     = su[t];
    const double Dc    = sd[t];
    const double Dprev = (t > 0) ? sd[t - 1] : 0.0;

    g_G[b][t] = (float)(P - Dprev);  // G_t = P_t - D_{t-1}
    g_H[b][t] = (float)(P - Dc);     // H_t = P_t - D_t
    g_D[b][t] = dv;
}

// ---------------------------------------------------------------------------
// Kernel 2: fused weights + gather. One warp per (t,b).
// ---------------------------------------------------------------------------
__global__ __launch_bounds__(WARPS * 32) void gather_kernel(
    const float* __restrict__ v, float* __restrict__ out) {
    const int tid  = threadIdx.x;
    const int warp = tid >> 5;
    const int lane = tid & 31;
    const int t    = blockIdx.x * WARPS + warp;
    const int b    = blockIdx.y;

    const float4* __restrict__ v4 = reinterpret_cast<const float4*>(v);
    float4* __restrict__ o4       = reinterpret_cast<float4*>(out);

    float4 r0 = make_float4(0.f, 0.f, 0.f, 0.f);
    float4 r1 = make_float4(0.f, 0.f, 0.f, 0.f);

    float carryM   = -1e30f;  // max of G over slots above current chunk
    float carryAcc = 0.f;     // strength consumed above current chunk

    for (int jtop = t; jtop >= 0 && carryAcc < 1.f; jtop -= 32) {
        const int  j  = jtop - lane;           // lane 0 = highest slot
        const bool ok = (j >= 0);

        const float Gj = ok ? g_G[b][j] : -1e30f;
        const float Hj = ok ? g_H[b][j] : 0.f;
        const float Dj = ok ? g_D[b][j] : 0.f;

        // Inclusive forward max-scan of G over lanes.
        float m = Gj;
        #pragma unroll
        for (int o = 1; o < 32; o <<= 1) {
            const float x = __shfl_up_sync(FULL, m, o);
            if (lane >= o) m = fmaxf(m, x);
        }
        // Exclusive version combined with the carry.
        float Me = __shfl_up_sync(FULL, m, 1);
        if (lane == 0) Me = -1e30f;
        Me = fmaxf(Me, carryM);

        // Per-slot surviving strength.
        const float s = ok ? fmaxf(Dj - fmaxf(Me - Hj, 0.f), 0.f) : 0.f;

        // Inclusive forward sum-scan of s over lanes.
        float a = s;
        #pragma unroll
        for (int o = 1; o < 32; o <<= 1) {
            const float x = __shfl_up_sync(FULL, a, o);
            if (lane >= o) a += x;
        }
        const float accInc = carryAcc + a;       // R consumed incl. this slot
        const float accExc = accInc - s;         // R consumed above this slot
        const float w = fminf(accInc, 1.f) - fminf(accExc, 1.f);

        // Gather the contributing rows (warp-uniform loop over set bits).
        unsigned mask = __ballot_sync(FULL, w > 0.f);
        while (mask) {
            const int src = __ffs(mask) - 1;
            mask &= mask - 1;
            const float wj = __shfl_sync(FULL, w, src);
            const int   jj = jtop - src;
            const float4* vp = v4 + ((size_t)jj * BB + b) * (EE / 4);
            const float4 a0 = __ldg(vp + lane);
            const float4 a1 = __ldg(vp + lane + 32);
            r0.x = fmaf(wj, a0.x, r0.x);
            r0.y = fmaf(wj, a0.y, r0.y);
            r0.z = fmaf(wj, a0.z, r0.z);
            r0.w = fmaf(wj, a0.w, r0.w);
            r1.x = fmaf(wj, a1.x, r1.x);
            r1.y = fmaf(wj, a1.y, r1.y);
            r1.z = fmaf(wj, a1.z, r1.z);
            r1.w = fmaf(wj, a1.w, r1.w);
        }

        // Warp-uniform carries for the next (lower) chunk.
        carryAcc = __shfl_sync(FULL, accInc, 31);
        carryM   = fmaxf(carryM, __shfl_sync(FULL, m, 31));
    }

    float4* op = o4 + ((size_t)t * BB + b) * (EE / 4);
    op[lane]      = r0;
    op[lane + 32] = r1;
}

extern "C" void kernel_launch(void* const* d_in, const int* in_sizes, int n_in,
                              void* d_out, int out_size) {
    const float* v = (const float*)d_in[0];  // [T,B,E]
    const float* u = (const float*)d_in[1];  // [T,B]
    const float* d = (const float*)d_in[2];  // [T,B]
    float* out     = (float*)d_out;          // [T,B,E]

    scan_kernel<<<BB, TT>>>(u, d);

    dim3 grid(TT / WARPS, BB);
    gather_kernel<<<grid, WARPS * 32>>>(v, out);
}